// round 1
// baseline (speedup 1.0000x reference)
#include <cuda_runtime.h>
#include <cuda_bf16.h>
#include <cstdint>

#define DIM 128
#define MAXV 100000

// Scratch (device globals; no allocation allowed)
__device__ float g_h[MAXV * DIM];      // h = emb @ W
__device__ float g_nodes[MAXV * DIM];  // aggregated output (pre-bias)
__device__ float g_deg[MAXV];
__device__ float g_dinv[MAXV];

// ---------------------------------------------------------------------------
// helpers: packed f32x2 FMA (Blackwell)
// ---------------------------------------------------------------------------
__device__ __forceinline__ unsigned long long ffma2(unsigned long long a,
                                                    unsigned long long b,
                                                    unsigned long long c) {
    unsigned long long d;
    asm("fma.rn.f32x2 %0, %1, %2, %3;" : "=l"(d) : "l"(a), "l"(b), "l"(c));
    return d;
}
__device__ __forceinline__ unsigned long long pack2(float x) {
    unsigned long long p;
    asm("mov.b64 %0, {%1, %1};" : "=l"(p) : "f"(x));
    return p;
}
__device__ __forceinline__ void unpack2(unsigned long long p, float& lo, float& hi) {
    asm("mov.b64 {%0, %1}, %2;" : "=f"(lo), "=f"(hi) : "l"(p));
}

// ---------------------------------------------------------------------------
// 1) degree: self-loop init + edge scatter + rsqrt
// ---------------------------------------------------------------------------
__global__ void k_init_deg(int V) {
    int v = blockIdx.x * blockDim.x + threadIdx.x;
    if (v < V) g_deg[v] = 1.0f;  // self-loop
}

__global__ void k_deg(const int* __restrict__ edge, int E) {
    int e = blockIdx.x * blockDim.x + threadIdx.x;
    if (e < E) atomicAdd(&g_deg[edge[E + e]], 1.0f);  // dst = edge_index[1]
}

__global__ void k_dinv(int V) {
    int v = blockIdx.x * blockDim.x + threadIdx.x;
    if (v < V) g_dinv[v] = rsqrtf(g_deg[v]);  // deg >= 1 always
}

// ---------------------------------------------------------------------------
// 2) GEMM: g_h = emb[V,128] @ W[128,128], fp32 accum via packed f32x2.
//    Block = 256 threads, 32 rows x 128 cols. Shared: W (64KB) + X tile (16KB).
// ---------------------------------------------------------------------------
__global__ void __launch_bounds__(256, 2) k_gemm(const float* __restrict__ X,
                                                 const float* __restrict__ W,
                                                 int V) {
    extern __shared__ float sh[];
    float* w_sh = sh;                 // [128][128]
    float* x_sh = sh + DIM * DIM;     // [32][128]

    const int tid  = threadIdx.x;
    const int row0 = blockIdx.x * 32;

    // load W (16384 floats = 4096 float4; 16 per thread)
    {
        const float4* W4 = reinterpret_cast<const float4*>(W);
        float4* w4 = reinterpret_cast<float4*>(w_sh);
#pragma unroll
        for (int i = 0; i < 16; i++) w4[tid + i * 256] = W4[tid + i * 256];
    }
    // load X tile (32 rows x 128 = 1024 float4; 4 per thread), guarded
    {
        const float4* X4 = reinterpret_cast<const float4*>(X) + (size_t)row0 * 32;
        float4* x4 = reinterpret_cast<float4*>(x_sh);
#pragma unroll
        for (int i = 0; i < 4; i++) {
            int idx = tid + i * 256;            // float4 index in tile
            int r = idx >> 5;                   // row within tile
            float4 v = make_float4(0.f, 0.f, 0.f, 0.f);
            if (row0 + r < V) v = X4[idx];
            x4[idx] = v;
        }
    }
    __syncthreads();

    const int cblk = tid & 31;   // column group: cols cblk*4 .. +3
    const int rblk = tid >> 5;   // row group:    rows rblk*4 .. +3

    unsigned long long acc[4][2];
#pragma unroll
    for (int r = 0; r < 4; r++) { acc[r][0] = 0ull; acc[r][1] = 0ull; }

    const float* xbase = x_sh + (rblk * 4) * DIM;

#pragma unroll 16
    for (int k = 0; k < DIM; k++) {
        // W row slice: float4 at w_sh[k*128 + cblk*4] -> two packed f32x2
        const ulonglong2 wv =
            *reinterpret_cast<const ulonglong2*>(w_sh + k * DIM + cblk * 4);
#pragma unroll
        for (int r = 0; r < 4; r++) {
            unsigned long long xp = pack2(xbase[r * DIM + k]);  // smem broadcast
            acc[r][0] = ffma2(xp, wv.x, acc[r][0]);
            acc[r][1] = ffma2(xp, wv.y, acc[r][1]);
        }
    }

#pragma unroll
    for (int r = 0; r < 4; r++) {
        int row = row0 + rblk * 4 + r;
        if (row < V) {
            float4 o;
            unpack2(acc[r][0], o.x, o.y);
            unpack2(acc[r][1], o.z, o.w);
            *reinterpret_cast<float4*>(g_h + (size_t)row * DIM + cblk * 4) = o;
        }
    }
}

// ---------------------------------------------------------------------------
// 3) self-loop init: nodes[v] = dinv[v]^2 * h[v]
// ---------------------------------------------------------------------------
__global__ void k_selfloop(int V) {
    int idx = blockIdx.x * blockDim.x + threadIdx.x;  // float4 index
    int total = V * 32;
    if (idx >= total) return;
    int v = idx >> 5;
    float s = g_dinv[v];
    s *= s;
    const float4 h = reinterpret_cast<const float4*>(g_h)[idx];
    float4 o;
    o.x = h.x * s; o.y = h.y * s; o.z = h.z * s; o.w = h.w * s;
    reinterpret_cast<float4*>(g_nodes)[idx] = o;
}

// ---------------------------------------------------------------------------
// 4) edge aggregation: one warp per edge, vector red.global.add.v4.f32
// ---------------------------------------------------------------------------
__global__ void __launch_bounds__(256) k_edge_agg(const int* __restrict__ edge, int E) {
    int warp = (blockIdx.x * blockDim.x + threadIdx.x) >> 5;
    int lane = threadIdx.x & 31;
    if (warp >= E) return;
    int src = __ldg(edge + warp);       // edge_index[0]
    int dst = __ldg(edge + E + warp);   // edge_index[1]
    float norm = g_dinv[src] * g_dinv[dst];
    const float4 v = reinterpret_cast<const float4*>(g_h)[(size_t)src * 32 + lane];
    float* p = g_nodes + (size_t)dst * DIM + lane * 4;
    asm volatile("red.global.add.v4.f32 [%0], {%1, %2, %3, %4};"
                 :: "l"(p), "f"(v.x * norm), "f"(v.y * norm),
                    "f"(v.z * norm), "f"(v.w * norm)
                 : "memory");
}

// ---------------------------------------------------------------------------
// 5) scoring: block = one item; 4 warps x 16 samples; bias folded in here.
//    scores[b,s] = dot(nodes[item]+bias, nodes[sample]+bias)
// ---------------------------------------------------------------------------
__global__ void __launch_bounds__(128) k_scores(const int* __restrict__ items,
                                                const int* __restrict__ samples,
                                                const float* __restrict__ bias,
                                                float* __restrict__ out, int S) {
    __shared__ float item_sh[DIM];
    __shared__ float bias_sh[DIM];
    const int b = blockIdx.x;
    const int t = threadIdx.x;

    const int item = __ldg(items + b);
    {
        float bv = __ldg(bias + t);
        bias_sh[t] = bv;
        item_sh[t] = g_nodes[(size_t)item * DIM + t] + bv;
    }
    __syncthreads();

    const int warp = t >> 5;
    const int lane = t & 31;
    const float4 iv = reinterpret_cast<const float4*>(item_sh)[lane];
    const float4 bv = reinterpret_cast<const float4*>(bias_sh)[lane];

    const int* samp = samples + (size_t)b * S;
#pragma unroll 4
    for (int i = 0; i < 16; i++) {
        int s = warp * 16 + i;
        int sidx = __ldg(samp + s);
        const float4 sv = reinterpret_cast<const float4*>(g_nodes)[(size_t)sidx * 32 + lane];
        float p = iv.x * (sv.x + bv.x) + iv.y * (sv.y + bv.y) +
                  iv.z * (sv.z + bv.z) + iv.w * (sv.w + bv.w);
#pragma unroll
        for (int off = 16; off > 0; off >>= 1)
            p += __shfl_xor_sync(0xffffffffu, p, off);
        if (lane == 0) out[(size_t)b * S + s] = p;
    }
}

// ---------------------------------------------------------------------------
// launcher
// ---------------------------------------------------------------------------
extern "C" void kernel_launch(void* const* d_in, const int* in_sizes, int n_in,
                              void* d_out, int out_size) {
    const int*   items   = (const int*)d_in[0];
    const int*   samples = (const int*)d_in[1];
    const int*   edge    = (const int*)d_in[2];
    const float* emb     = (const float*)d_in[3];
    const float* W       = (const float*)d_in[4];
    const float* bias    = (const float*)d_in[5];
    float*       out     = (float*)d_out;

    const int B = in_sizes[0];
    const int S = in_sizes[1] / B;
    const int E = in_sizes[2] / 2;
    const int V = in_sizes[3] / DIM;

    // deg / dinv
    k_init_deg<<<(V + 255) / 256, 256>>>(V);
    k_deg<<<(E + 255) / 256, 256>>>(edge, E);
    k_dinv<<<(V + 255) / 256, 256>>>(V);

    // GEMM h = emb @ W (80 KB dynamic shared)
    const int gemm_smem = (DIM * DIM + 32 * DIM) * (int)sizeof(float);  // 81920
    cudaFuncSetAttribute(k_gemm, cudaFuncAttributeMaxDynamicSharedMemorySize, gemm_smem);
    k_gemm<<<(V + 31) / 32, 256, gemm_smem>>>(emb, W, V);

    // self-loop init + edge scatter-add
    k_selfloop<<<(V * 32 + 255) / 256, 256>>>(V);
    k_edge_agg<<<(E + 7) / 8, 256>>>(edge, E);

    // scoring with folded bias
    k_scores<<<B, 128>>>(items, samples, bias, out, S);
}